// round 2
// baseline (speedup 1.0000x reference)
#include <cuda_runtime.h>
#include <cstdint>

#define NN 50000
#define F 128
#define NCLS 40

// Scratch (allocation-free rule: __device__ globals)
__device__ float g_p[NN * F];     // projected messages (layer2 uses first NN*40)
__device__ float g_agg[NN * F];   // aggregation target (layer2 uses first NN*40)
__device__ float g_h[NN * F];     // hidden activations
__device__ float g_deg[NN];       // in-degree (float)
__device__ int   g_mode32;        // 1 if edge_index is int32, 0 if int64

// ---------------------------------------------------------------------------
// Detect edge_index dtype: if the first 16 values interpreted as int64 are all
// in [0, NN), it's int64; otherwise int32. (int32 data read as int64 packs two
// lanes -> almost surely out of range for at least one of 16 probes.)
__global__ void detect_kernel(const void* ei) {
    if (threadIdx.x == 0 && blockIdx.x == 0) {
        const long long* p = (const long long*)ei;
        int m32 = 0;
        for (int i = 0; i < 16; i++) {
            long long v = p[i];
            if (v < 0 || v >= NN) { m32 = 1; break; }
        }
        g_mode32 = m32;
    }
}

// ---------------------------------------------------------------------------
__global__ void zero_kernel(float4* __restrict__ p, int n4) {
    int i = blockIdx.x * blockDim.x + threadIdx.x;
    int stride = gridDim.x * blockDim.x;
    float4 z = make_float4(0.f, 0.f, 0.f, 0.f);
    for (; i < n4; i += stride) p[i] = z;
}

// ---------------------------------------------------------------------------
// Scatter: for each edge e, agg[dst[e]] += feat[src[e]]  (W floats per row).
// One thread handles one float4 chunk. For W=128 a warp covers exactly one
// edge row (512B coalesced). Optionally accumulates degree.
template <int W, bool COUNT_DEG>
__global__ void scatter_kernel(const void* __restrict__ ei,
                               const float* __restrict__ feat,
                               float* __restrict__ agg,
                               float* __restrict__ deg,
                               int E) {
    constexpr int CH = W / 4;
    const int mode32 = g_mode32;
    long long total = (long long)E * CH;
    long long stride = (long long)gridDim.x * blockDim.x;
    for (long long t = (long long)blockIdx.x * blockDim.x + threadIdx.x;
         t < total; t += stride) {
        int e = (int)(t / CH);
        int c = (int)(t % CH);
        int s, d;
        if (mode32) {
            const int* p = (const int*)ei;
            s = p[e]; d = p[E + e];
        } else {
            const long long* p = (const long long*)ei;
            s = (int)p[e]; d = (int)p[E + e];
        }
        float4 v = ((const float4*)(feat + (long long)s * W))[c];
        float4* dp = (float4*)(agg + (long long)d * W) + c;
        asm volatile("red.global.add.v4.f32 [%0], {%1,%2,%3,%4};"
                     :: "l"(dp), "f"(v.x), "f"(v.y), "f"(v.z), "f"(v.w)
                     : "memory");
        if (COUNT_DEG && c == 0) atomicAdd(&deg[d], 1.0f);
    }
}

// ---------------------------------------------------------------------------
// Tiled GEMM: C[N x NC] = A[N x 128] @ Wm[128 x NC]
//   optional epilogue: + agg[row]*1/max(deg,1) + bias, optional relu.
// BM=64, BK=32, 256 threads, TM=4, TN=BN/16.
template <int BN, int NC, bool ADD_AGG, bool HAS_BIAS, bool RELU>
__global__ __launch_bounds__(256)
void gemm_kernel(const float* __restrict__ A,
                 const float* __restrict__ Wm,
                 const float* __restrict__ bias,
                 const float* __restrict__ agg,
                 const float* __restrict__ deg,
                 float* __restrict__ C,
                 int Nrows) {
    constexpr int BM = 64, BK = 32, TM = 4, TN = BN / 16;
    __shared__ float As[BK][BM + 1];   // +1 pad: conflict-free transp. store/read
    __shared__ float Bs[BK][BN];

    int tid = threadIdx.x;
    int tx = tid & 15;        // col group (16)
    int ty = tid >> 4;        // row group (16)
    int brow = blockIdx.x * BM;

    float acc[TM][TN];
#pragma unroll
    for (int i = 0; i < TM; i++)
#pragma unroll
        for (int j = 0; j < TN; j++) acc[i][j] = 0.0f;

#pragma unroll
    for (int kc = 0; kc < F; kc += BK) {
        // Load A tile (BM x BK = 2048 elems, 8 per thread), transposed store
#pragma unroll
        for (int p = 0; p < (BM * BK / 256); p++) {
            int idx = tid + p * 256;
            int k = idx & 31;
            int r = idx >> 5;
            int row = brow + r;
            As[k][r] = (row < Nrows) ? A[(long long)row * F + kc + k] : 0.0f;
        }
        // Load W tile (BK x BN), zero-pad cols >= NC
#pragma unroll
        for (int p = 0; p < (BK * BN / 256); p++) {
            int idx = tid + p * 256;
            int col = idx % BN;
            int kr = idx / BN;
            float v = 0.0f;
            if (col < NC) v = Wm[(kc + kr) * NC + col];
            Bs[kr][col] = v;
        }
        __syncthreads();
#pragma unroll
        for (int kk = 0; kk < BK; kk++) {
            float a[TM], b[TN];
#pragma unroll
            for (int i = 0; i < TM; i++) a[i] = As[kk][ty + i * 16];
#pragma unroll
            for (int j = 0; j < TN; j++) b[j] = Bs[kk][tx + j * 16];
#pragma unroll
            for (int i = 0; i < TM; i++)
#pragma unroll
                for (int j = 0; j < TN; j++) acc[i][j] += a[i] * b[j];
        }
        __syncthreads();
    }

    // Epilogue
#pragma unroll
    for (int i = 0; i < TM; i++) {
        int row = brow + ty + i * 16;
        if (row >= Nrows) continue;
        float inv = 0.0f;
        if (ADD_AGG) {
            float dg = deg[row];
            inv = 1.0f / fmaxf(dg, 1.0f);
        }
#pragma unroll
        for (int j = 0; j < TN; j++) {
            int col = tx + j * 16;
            if (col >= NC) continue;
            float v = acc[i][j];
            if (ADD_AGG) v += agg[(long long)row * NC + col] * inv;
            if (HAS_BIAS) v += bias[col];
            if (RELU) v = fmaxf(v, 0.0f);
            C[(long long)row * NC + col] = v;
        }
    }
}

// ---------------------------------------------------------------------------
extern "C" void kernel_launch(void* const* d_in, const int* in_sizes, int n_in,
                              void* d_out, int out_size) {
    const float* x   = (const float*)d_in[0];
    const void*  ei  = d_in[1];
    const float* w1l = (const float*)d_in[2];
    const float* w1r = (const float*)d_in[3];
    const float* b1  = (const float*)d_in[4];
    const float* w2l = (const float*)d_in[5];
    const float* w2r = (const float*)d_in[6];
    const float* b2  = (const float*)d_in[7];
    float* out = (float*)d_out;

    int E = in_sizes[1] / 2;
    int N = in_sizes[0] / F;   // 50000

    float *pP, *pAgg, *pH, *pDeg;
    cudaGetSymbolAddress((void**)&pP,   g_p);
    cudaGetSymbolAddress((void**)&pAgg, g_agg);
    cudaGetSymbolAddress((void**)&pH,   g_h);
    cudaGetSymbolAddress((void**)&pDeg, g_deg);

    const int T = 256;
    int gemm_blocks = (N + 63) / 64;

    // 0) edge dtype detect
    detect_kernel<<<1, 32>>>(ei);

    // 1) zero agg (N*F) and deg (N)  (deg: N divisible by 4)
    zero_kernel<<<(N * F / 4 + T - 1) / T, T>>>((float4*)pAgg, N * F / 4);
    zero_kernel<<<(N / 4 + T - 1) / T, T>>>((float4*)pDeg, N / 4);

    // 2) p = x @ w1_l
    gemm_kernel<128, 128, false, false, false><<<gemm_blocks, T>>>(
        x, w1l, nullptr, nullptr, nullptr, pP, N);

    // 3) scatter p[src] -> agg[dst], count deg
    {
        long long total = (long long)E * 32;
        int blocks = (int)((total + T - 1) / T);
        if (blocks > 65535 * 8) blocks = 65535 * 8;
        scatter_kernel<128, true><<<blocks, T>>>(ei, pP, pAgg, pDeg, E);
    }

    // 4) h = relu(agg*invdeg + x @ w1_r + b1)
    gemm_kernel<128, 128, true, true, true><<<gemm_blocks, T>>>(
        x, w1r, b1, pAgg, pDeg, pH, N);

    // 5) p = h @ w2_l   (N x 40)
    gemm_kernel<64, NCLS, false, false, false><<<gemm_blocks, T>>>(
        pH, w2l, nullptr, nullptr, nullptr, pP, N);

    // 6) zero agg (N*40), scatter p -> agg (40 floats / edge)
    zero_kernel<<<(N * NCLS / 4 + T - 1) / T, T>>>((float4*)pAgg, N * NCLS / 4);
    {
        long long total = (long long)E * (NCLS / 4);
        int blocks = (int)((total + T - 1) / T);
        scatter_kernel<NCLS, false><<<blocks, T>>>(ei, pP, pAgg, nullptr, E);
    }

    // 7) out = agg*invdeg + h @ w2_r + b2
    gemm_kernel<64, NCLS, true, true, false><<<gemm_blocks, T>>>(
        pH, w2r, b2, pAgg, pDeg, out, N);
}

// round 3
// speedup vs baseline: 1.1709x; 1.1709x over previous
#include <cuda_runtime.h>
#include <cstdint>

#define NN 50000
#define F 128
#define NCLS 40
#define MAXE 600000

// Scratch (allocation-free rule: __device__ globals)
__device__ float g_p[NN * F];     // projected messages (layer2 uses first NN*40)
__device__ float g_agg[NN * F];   // aggregation target (layer2 uses first NN*40)
__device__ float g_h[NN * F];     // hidden activations
__device__ float g_deg[NN];       // in-degree (float)
__device__ int   g_src[MAXE];     // int32 src indices
__device__ int   g_dst[MAXE];     // int32 dst indices
__device__ int   g_mode32;        // 1 if edge_index is int32, 0 if int64

// ---------------------------------------------------------------------------
// Detect edge_index dtype: if the first 16 values interpreted as int64 are all
// in [0, NN), it's int64; otherwise int32.
__global__ void detect_kernel(const void* ei) {
    if (threadIdx.x == 0 && blockIdx.x == 0) {
        const long long* p = (const long long*)ei;
        int m32 = 0;
        for (int i = 0; i < 16; i++) {
            long long v = p[i];
            if (v < 0 || v >= NN) { m32 = 1; break; }
        }
        g_mode32 = m32;
    }
}

// ---------------------------------------------------------------------------
// Convert indices to int32 and accumulate in-degree (deg must be pre-zeroed).
__global__ void convert_idx_kernel(const void* __restrict__ ei,
                                   int* __restrict__ src32,
                                   int* __restrict__ dst32,
                                   float* __restrict__ deg, int E) {
    const int mode32 = g_mode32;
    int stride = gridDim.x * blockDim.x;
    for (int e = blockIdx.x * blockDim.x + threadIdx.x; e < E; e += stride) {
        int s, d;
        if (mode32) {
            const int* p = (const int*)ei;
            s = p[e]; d = p[E + e];
        } else {
            const long long* p = (const long long*)ei;
            s = (int)p[e]; d = (int)p[E + e];
        }
        src32[e] = s;
        dst32[e] = d;
        atomicAdd(&deg[d], 1.0f);
    }
}

// ---------------------------------------------------------------------------
// Zero two float ranges in one launch.
__global__ void zero2_kernel(float4* __restrict__ p1, int n1,
                             float4* __restrict__ p2, int n2) {
    int stride = gridDim.x * blockDim.x;
    float4 z = make_float4(0.f, 0.f, 0.f, 0.f);
    int total = n1 + n2;
    for (int i = blockIdx.x * blockDim.x + threadIdx.x; i < total; i += stride) {
        if (i < n1) p1[i] = z;
        else        p2[i - n1] = z;
    }
}

// ---------------------------------------------------------------------------
// Scatter: for each edge e, agg[dst[e]] += feat[src[e]]  (W floats per row).
// One thread per float4 chunk; for W=128 a warp covers exactly one edge.
template <int W>
__global__ void scatter_kernel(const int* __restrict__ src,
                               const int* __restrict__ dst,
                               const float* __restrict__ feat,
                               float* __restrict__ agg, int E) {
    constexpr int CH = W / 4;
    long long total = (long long)E * CH;
    long long stride = (long long)gridDim.x * blockDim.x;
    for (long long t = (long long)blockIdx.x * blockDim.x + threadIdx.x;
         t < total; t += stride) {
        int e = (int)(t / CH);
        int c = (int)(t % CH);
        int s = src[e];
        int d = dst[e];
        float4 v = ((const float4*)(feat + (long long)s * W))[c];
        float4* dp = (float4*)(agg + (long long)d * W) + c;
        asm volatile("red.global.add.v4.f32 [%0], {%1,%2,%3,%4};"
                     :: "l"(dp), "f"(v.x), "f"(v.y), "f"(v.z), "f"(v.w)
                     : "memory");
    }
}

// ---------------------------------------------------------------------------
// Register-blocked SGEMM: C[N x NC] = A[N x 128] @ Wm[128 x NC]
// BM=128, BK=8, 256 threads. Column coverage = 64*HALVES (HALVES=2 -> 128).
// Each thread: rows {ty*4+i, 64+ty*4+i}, cols {ch*64 + tx*4+j}.
// Epilogue: optional + agg[row]*1/max(deg,1) + bias, optional relu.
template <int NC, int HALVES, bool ADD_AGG, bool HAS_BIAS, bool RELU>
__global__ __launch_bounds__(256, 2)
void gemm_kernel(const float* __restrict__ A,
                 const float* __restrict__ Wm,
                 const float* __restrict__ bias,
                 const float* __restrict__ agg,
                 const float* __restrict__ deg,
                 float* __restrict__ C,
                 int Nrows) {
    constexpr int BM = 128, BK = 8;
    constexpr int BNW = 64 * HALVES;
    __shared__ float As[BK][BM + 4];   // pad 4: conflict-free transposed stores
    __shared__ float Bs[BK][BNW];

    int tid = threadIdx.x;
    int tx = tid & 15;         // col group
    int ty = tid >> 4;         // row group
    int brow = blockIdx.x * BM;

    // A load mapping: one float4 per thread per iter
    int ar  = tid >> 1;              // 0..127
    int ak4 = (tid & 1) * 4;         // 0 or 4
    bool a_valid = (brow + ar) < Nrows;
    const float* a_ptr = A + (long long)(brow + ar) * F + ak4;

    float acc[2][HALVES][4][4];
#pragma unroll
    for (int rh = 0; rh < 2; rh++)
#pragma unroll
        for (int ch = 0; ch < HALVES; ch++)
#pragma unroll
            for (int i = 0; i < 4; i++)
#pragma unroll
                for (int j = 0; j < 4; j++) acc[rh][ch][i][j] = 0.0f;

    for (int kc = 0; kc < F; kc += BK) {
        // --- load A tile (128 x 8), transposed into As[k][row]
        float4 av = make_float4(0.f, 0.f, 0.f, 0.f);
        if (a_valid) av = *(const float4*)(a_ptr + kc);
        As[ak4 + 0][ar] = av.x;
        As[ak4 + 1][ar] = av.y;
        As[ak4 + 2][ar] = av.z;
        As[ak4 + 3][ar] = av.w;
        // --- load B tile (8 x BNW), zero-pad cols >= NC
        if (HALVES == 2) {
            int bk = tid >> 5;           // 0..7
            int bc4 = (tid & 31) * 4;    // 0..124
            float4 bv = make_float4(0.f, 0.f, 0.f, 0.f);
            if (bc4 < NC) bv = *(const float4*)(Wm + (kc + bk) * NC + bc4);
            *(float4*)&Bs[bk][bc4] = bv;
        } else {
            if (tid < 128) {
                int bk = tid >> 4;           // 0..7
                int bc4 = (tid & 15) * 4;    // 0..60
                float4 bv = make_float4(0.f, 0.f, 0.f, 0.f);
                if (bc4 < NC) bv = *(const float4*)(Wm + (kc + bk) * NC + bc4);
                *(float4*)&Bs[bk][bc4] = bv;
            }
        }
        __syncthreads();
#pragma unroll
        for (int kk = 0; kk < BK; kk++) {
            float4 a0 = *(const float4*)&As[kk][ty * 4];
            float4 a1 = *(const float4*)&As[kk][64 + ty * 4];
            float ar_[2][4] = {{a0.x, a0.y, a0.z, a0.w}, {a1.x, a1.y, a1.z, a1.w}};
            float bc_[HALVES][4];
            float4 b0 = *(const float4*)&Bs[kk][tx * 4];
            bc_[0][0] = b0.x; bc_[0][1] = b0.y; bc_[0][2] = b0.z; bc_[0][3] = b0.w;
            if (HALVES == 2) {
                float4 b1 = *(const float4*)&Bs[kk][64 + tx * 4];
                bc_[1][0] = b1.x; bc_[1][1] = b1.y; bc_[1][2] = b1.z; bc_[1][3] = b1.w;
            }
#pragma unroll
            for (int rh = 0; rh < 2; rh++)
#pragma unroll
                for (int ch = 0; ch < HALVES; ch++)
#pragma unroll
                    for (int i = 0; i < 4; i++)
#pragma unroll
                        for (int j = 0; j < 4; j++)
                            acc[rh][ch][i][j] += ar_[rh][i] * bc_[ch][j];
        }
        __syncthreads();
    }

    // Epilogue
#pragma unroll
    for (int rh = 0; rh < 2; rh++) {
#pragma unroll
        for (int i = 0; i < 4; i++) {
            int row = brow + rh * 64 + ty * 4 + i;
            if (row >= Nrows) continue;
            float inv = 0.0f;
            if (ADD_AGG) inv = 1.0f / fmaxf(deg[row], 1.0f);
#pragma unroll
            for (int ch = 0; ch < HALVES; ch++) {
                int col = ch * 64 + tx * 4;
                if (col >= NC) continue;
                float4 v;
                v.x = acc[rh][ch][i][0];
                v.y = acc[rh][ch][i][1];
                v.z = acc[rh][ch][i][2];
                v.w = acc[rh][ch][i][3];
                if (ADD_AGG) {
                    float4 ag = *(const float4*)(agg + (long long)row * NC + col);
                    v.x += ag.x * inv; v.y += ag.y * inv;
                    v.z += ag.z * inv; v.w += ag.w * inv;
                }
                if (HAS_BIAS) {
                    float4 bv = *(const float4*)(bias + col);
                    v.x += bv.x; v.y += bv.y; v.z += bv.z; v.w += bv.w;
                }
                if (RELU) {
                    v.x = fmaxf(v.x, 0.f); v.y = fmaxf(v.y, 0.f);
                    v.z = fmaxf(v.z, 0.f); v.w = fmaxf(v.w, 0.f);
                }
                *(float4*)(C + (long long)row * NC + col) = v;
            }
        }
    }
}

// ---------------------------------------------------------------------------
extern "C" void kernel_launch(void* const* d_in, const int* in_sizes, int n_in,
                              void* d_out, int out_size) {
    const float* x   = (const float*)d_in[0];
    const void*  ei  = d_in[1];
    const float* w1l = (const float*)d_in[2];
    const float* w1r = (const float*)d_in[3];
    const float* b1  = (const float*)d_in[4];
    const float* w2l = (const float*)d_in[5];
    const float* w2r = (const float*)d_in[6];
    const float* b2  = (const float*)d_in[7];
    float* out = (float*)d_out;

    int E = in_sizes[1] / 2;
    int N = in_sizes[0] / F;   // 50000

    float *pP, *pAgg, *pH, *pDeg;
    int *pSrc, *pDst;
    cudaGetSymbolAddress((void**)&pP,   g_p);
    cudaGetSymbolAddress((void**)&pAgg, g_agg);
    cudaGetSymbolAddress((void**)&pH,   g_h);
    cudaGetSymbolAddress((void**)&pDeg, g_deg);
    cudaGetSymbolAddress((void**)&pSrc, g_src);
    cudaGetSymbolAddress((void**)&pDst, g_dst);

    const int T = 256;
    int gemm_blocks = (N + 127) / 128;

    // 0) zero agg (N*F) and deg (N) in one launch
    zero2_kernel<<<(N * F / 4 + N / 4 + T - 1) / T, T>>>(
        (float4*)pAgg, N * F / 4, (float4*)pDeg, N / 4);

    // 1) edge dtype detect, then index conversion + degree count
    detect_kernel<<<1, 32>>>(ei);
    convert_idx_kernel<<<(E + T - 1) / T, T>>>(ei, pSrc, pDst, pDeg, E);

    // 2) p = x @ w1_l
    gemm_kernel<128, 2, false, false, false><<<gemm_blocks, T>>>(
        x, w1l, nullptr, nullptr, nullptr, pP, N);

    // 3) scatter p[src] -> agg[dst]
    {
        long long total = (long long)E * 32;
        int blocks = (int)((total + T - 1) / T);
        if (blocks > 65535 * 8) blocks = 65535 * 8;
        scatter_kernel<128><<<blocks, T>>>(pSrc, pDst, pP, pAgg, E);
    }

    // 4) h = relu(agg*invdeg + x @ w1_r + b1)
    gemm_kernel<128, 2, true, true, true><<<gemm_blocks, T>>>(
        x, w1r, b1, pAgg, pDeg, pH, N);

    // 5) q = h @ w2_l   (N x 40)
    gemm_kernel<NCLS, 1, false, false, false><<<gemm_blocks, T>>>(
        pH, w2l, nullptr, nullptr, nullptr, pP, N);

    // 6) zero agg (N*40), scatter q -> agg (40 floats / edge)
    zero2_kernel<<<(N * NCLS / 4 + T - 1) / T, T>>>(
        (float4*)pAgg, N * NCLS / 4, (float4*)pAgg, 0);
    {
        long long total = (long long)E * (NCLS / 4);
        int blocks = (int)((total + T - 1) / T);
        if (blocks > 65535 * 8) blocks = 65535 * 8;
        scatter_kernel<NCLS><<<blocks, T>>>(pSrc, pDst, pP, pAgg, E);
    }

    // 7) out = agg*invdeg + h @ w2_r + b2
    gemm_kernel<NCLS, 1, true, true, false><<<gemm_blocks, T>>>(
        pH, w2r, b2, pAgg, pDeg, out, N);
}

// round 4
// speedup vs baseline: 1.5315x; 1.3080x over previous
#include <cuda_runtime.h>
#include <cstdint>

#define NN   50000
#define F    128
#define NCLS 40
#define MAXE 600000
#define SCB  512
#define NSB  ((NN + SCB - 1) / SCB)   // 98

// ---------------- scratch (__device__ globals; no allocations) -------------
__device__ float g_pt[NN * 256];     // [p | t] layer1; reused as q/u layer2
__device__ float g_h[NN * F];        // hidden activations
__device__ float g_wcat[F * 256];    // [w1l | w1r]
__device__ int g_src[MAXE], g_dst[MAXE], g_csr[MAXE];
__device__ int g_cnt[NN], g_fill[NN], g_offs[NN], g_incl[NN];
__device__ int g_bsum[NSB], g_bexc[NSB];
__device__ int g_mode32;

// ---------------------------------------------------------------------------
__global__ void detect_kernel(const void* ei) {
    if (threadIdx.x == 0 && blockIdx.x == 0) {
        const long long* p = (const long long*)ei;
        int m32 = 0;
        for (int i = 0; i < 16; i++) {
            long long v = p[i];
            if (v < 0 || v >= NN) { m32 = 1; break; }
        }
        g_mode32 = m32;
    }
}

// zero two int arrays of n each
__global__ void zero_int2_kernel(int4* a, int4* b, int n4) {
    int i = blockIdx.x * blockDim.x + threadIdx.x;
    int stride = gridDim.x * blockDim.x;
    int4 z = make_int4(0, 0, 0, 0);
    for (; i < 2 * n4; i += stride) {
        if (i < n4) a[i] = z; else b[i - n4] = z;
    }
}

__global__ void build_wcat_kernel(const float* __restrict__ w1l,
                                  const float* __restrict__ w1r,
                                  float* __restrict__ wcat) {
    int i = blockIdx.x * blockDim.x + threadIdx.x;
    if (i < F * 256) {
        int k = i >> 8, c = i & 255;
        wcat[i] = (c < 128) ? w1l[k * 128 + c] : w1r[k * 128 + (c - 128)];
    }
}

// convert indices to int32 + histogram in-degree
__global__ void hist_kernel(const void* __restrict__ ei,
                            int* __restrict__ src32, int* __restrict__ dst32,
                            int* __restrict__ cnt, int E) {
    const int mode32 = g_mode32;
    int stride = gridDim.x * blockDim.x;
    for (int e = blockIdx.x * blockDim.x + threadIdx.x; e < E; e += stride) {
        int s, d;
        if (mode32) {
            const int* p = (const int*)ei;
            s = p[e]; d = p[E + e];
        } else {
            const long long* p = (const long long*)ei;
            s = (int)p[e]; d = (int)p[E + e];
        }
        src32[e] = s;
        dst32[e] = d;
        atomicAdd(&cnt[d], 1);
    }
}

// --------- 3-kernel exclusive scan of g_cnt -> g_offs ----------------------
__global__ void scan1_kernel(const int* __restrict__ cnt,
                             int* __restrict__ incl, int* __restrict__ bsum) {
    __shared__ int sm[SCB];
    int t = threadIdx.x;
    int i = blockIdx.x * SCB + t;
    int v = (i < NN) ? cnt[i] : 0;
    sm[t] = v;
    __syncthreads();
    for (int off = 1; off < SCB; off <<= 1) {
        int x = (t >= off) ? sm[t - off] : 0;
        __syncthreads();
        sm[t] += x;
        __syncthreads();
    }
    if (i < NN) incl[i] = sm[t];
    if (t == SCB - 1) bsum[blockIdx.x] = sm[t];
}

__global__ void scan2_kernel(const int* __restrict__ bsum, int* __restrict__ bexc) {
    __shared__ int sm[128];
    int t = threadIdx.x;
    int v = (t < NSB) ? bsum[t] : 0;
    sm[t] = v;
    __syncthreads();
    for (int off = 1; off < 128; off <<= 1) {
        int x = (t >= off) ? sm[t - off] : 0;
        __syncthreads();
        sm[t] += x;
        __syncthreads();
    }
    if (t < NSB) bexc[t] = sm[t] - v;   // exclusive
}

__global__ void scan3_kernel(const int* __restrict__ incl,
                             const int* __restrict__ cnt,
                             const int* __restrict__ bexc,
                             int* __restrict__ offs) {
    int i = blockIdx.x * blockDim.x + threadIdx.x;
    if (i < NN) offs[i] = incl[i] - cnt[i] + bexc[i >> 9];
}

__global__ void fill_kernel(const int* __restrict__ src32,
                            const int* __restrict__ dst32,
                            const int* __restrict__ offs,
                            int* __restrict__ fill, int* __restrict__ csr, int E) {
    int stride = gridDim.x * blockDim.x;
    for (int e = blockIdx.x * blockDim.x + threadIdx.x; e < E; e += stride) {
        int d = dst32[e];
        int slot = offs[d] + atomicAdd(&fill[d], 1);
        csr[slot] = src32[e];
    }
}

// ---------------------------------------------------------------------------
// Register-blocked SGEMM: C[N x ...] = A[N x 128] @ B
// BM=128, BK=8, 256 threads. HALVES: number of 64-col sub-blocks handled.
// SWB: row stride of B, SWC: row stride of C, NCV: valid columns (guards).
// colbase = blockIdx.y * 128.
template <int HALVES, int SWB, int SWC, int NCV>
__global__ __launch_bounds__(256, 2)
void gemm_kernel(const float* __restrict__ A,
                 const float* __restrict__ B,
                 float* __restrict__ C,
                 int Nrows) {
    constexpr int BM = 128, BK = 8;
    __shared__ float As[BK][BM + 4];
    __shared__ float Bs[BK][64 * HALVES];

    int tid = threadIdx.x;
    int tx = tid & 15;
    int ty = tid >> 4;
    int brow = blockIdx.x * BM;
    int colbase = blockIdx.y * 128;

    int ar = tid >> 1;
    int ak4 = (tid & 1) * 4;
    bool a_valid = (brow + ar) < Nrows;
    const float* a_ptr = A + (long long)(brow + ar) * F + ak4;

    float acc[2][HALVES][4][4];
#pragma unroll
    for (int rh = 0; rh < 2; rh++)
#pragma unroll
        for (int ch = 0; ch < HALVES; ch++)
#pragma unroll
            for (int i = 0; i < 4; i++)
#pragma unroll
                for (int j = 0; j < 4; j++) acc[rh][ch][i][j] = 0.0f;

    for (int kc = 0; kc < F; kc += BK) {
        // A tile (128x8) transposed
        float4 av = make_float4(0.f, 0.f, 0.f, 0.f);
        if (a_valid) av = *(const float4*)(a_ptr + kc);
        As[ak4 + 0][ar] = av.x;
        As[ak4 + 1][ar] = av.y;
        As[ak4 + 2][ar] = av.z;
        As[ak4 + 3][ar] = av.w;
        // B tile (8 x 64*HALVES)
        if (HALVES == 2) {
            int bk = tid >> 5;
            int bc4 = (tid & 31) * 4;
            float4 bv = make_float4(0.f, 0.f, 0.f, 0.f);
            int col = colbase + bc4;
            if (col < NCV) bv = *(const float4*)(B + (long long)(kc + bk) * SWB + col);
            *(float4*)&Bs[bk][bc4] = bv;
        } else {
            if (tid < 128) {
                int bk = tid >> 4;
                int bc4 = (tid & 15) * 4;
                float4 bv = make_float4(0.f, 0.f, 0.f, 0.f);
                if (bc4 < NCV) bv = *(const float4*)(B + (long long)(kc + bk) * SWB + bc4);
                *(float4*)&Bs[bk][bc4] = bv;
            }
        }
        __syncthreads();
#pragma unroll
        for (int kk = 0; kk < BK; kk++) {
            float4 a0 = *(const float4*)&As[kk][ty * 4];
            float4 a1 = *(const float4*)&As[kk][64 + ty * 4];
            float ar_[2][4] = {{a0.x, a0.y, a0.z, a0.w}, {a1.x, a1.y, a1.z, a1.w}};
            float bc_[HALVES][4];
            float4 b0 = *(const float4*)&Bs[kk][tx * 4];
            bc_[0][0] = b0.x; bc_[0][1] = b0.y; bc_[0][2] = b0.z; bc_[0][3] = b0.w;
            if (HALVES == 2) {
                float4 b1 = *(const float4*)&Bs[kk][64 + tx * 4];
                bc_[1][0] = b1.x; bc_[1][1] = b1.y; bc_[1][2] = b1.z; bc_[1][3] = b1.w;
            }
#pragma unroll
            for (int rh = 0; rh < 2; rh++)
#pragma unroll
                for (int ch = 0; ch < HALVES; ch++)
#pragma unroll
                    for (int i = 0; i < 4; i++)
#pragma unroll
                        for (int j = 0; j < 4; j++)
                            acc[rh][ch][i][j] += ar_[rh][i] * bc_[ch][j];
        }
        __syncthreads();
    }

#pragma unroll
    for (int rh = 0; rh < 2; rh++) {
#pragma unroll
        for (int i = 0; i < 4; i++) {
            int row = brow + rh * 64 + ty * 4 + i;
            if (row >= Nrows) continue;
#pragma unroll
            for (int ch = 0; ch < HALVES; ch++) {
                int col = colbase + ch * 64 + tx * 4;
                if (col >= NCV) continue;
                float4 v;
                v.x = acc[rh][ch][i][0];
                v.y = acc[rh][ch][i][1];
                v.z = acc[rh][ch][i][2];
                v.w = acc[rh][ch][i][3];
                *(float4*)(C + (long long)row * SWC + col) = v;
            }
        }
    }
}

// ---------------------------------------------------------------------------
// Layer-1 aggregation + epilogue: h[n] = relu(mean_{s in N(n)} p[s] + t[n] + b1)
// p = pt[:, 0:128], t = pt[:, 128:256]. One warp per node; lane owns float4.
__global__ void agg1_kernel(const int* __restrict__ csr,
                            const int* __restrict__ offs,
                            const int* __restrict__ cnt,
                            const float* __restrict__ pt,
                            const float* __restrict__ b1,
                            float* __restrict__ h) {
    int gw = (blockIdx.x * blockDim.x + threadIdx.x) >> 5;
    int lane = threadIdx.x & 31;
    if (gw >= NN) return;
    int beg = offs[gw];
    int dg = cnt[gw];
    float4 acc = make_float4(0.f, 0.f, 0.f, 0.f);
    for (int i = 0; i < dg; i++) {
        int s = csr[beg + i];
        float4 v = *(const float4*)(pt + (long long)s * 256 + lane * 4);
        acc.x += v.x; acc.y += v.y; acc.z += v.z; acc.w += v.w;
    }
    float inv = 1.0f / fmaxf((float)dg, 1.0f);
    float4 t = *(const float4*)(pt + (long long)gw * 256 + 128 + lane * 4);
    float4 bb = *(const float4*)(b1 + lane * 4);
    float4 r;
    r.x = fmaxf(acc.x * inv + t.x + bb.x, 0.f);
    r.y = fmaxf(acc.y * inv + t.y + bb.y, 0.f);
    r.z = fmaxf(acc.z * inv + t.z + bb.z, 0.f);
    r.w = fmaxf(acc.w * inv + t.w + bb.w, 0.f);
    *(float4*)(h + (long long)gw * F + lane * 4) = r;
}

// Layer-2 aggregation + epilogue: out[n] = mean q[s] + u[n] + b2   (40 floats)
__global__ void agg2_kernel(const int* __restrict__ csr,
                            const int* __restrict__ offs,
                            const int* __restrict__ cnt,
                            const float* __restrict__ q,
                            const float* __restrict__ u,
                            const float* __restrict__ b2,
                            float* __restrict__ out) {
    int gw = (blockIdx.x * blockDim.x + threadIdx.x) >> 5;
    int lane = threadIdx.x & 31;
    if (gw >= NN) return;
    int beg = offs[gw];
    int dg = cnt[gw];
    if (lane < 10) {
        float4 acc = make_float4(0.f, 0.f, 0.f, 0.f);
        for (int i = 0; i < dg; i++) {
            int s = csr[beg + i];
            float4 v = *(const float4*)(q + (long long)s * NCLS + lane * 4);
            acc.x += v.x; acc.y += v.y; acc.z += v.z; acc.w += v.w;
        }
        float inv = 1.0f / fmaxf((float)dg, 1.0f);
        float4 uv = *(const float4*)(u + (long long)gw * NCLS + lane * 4);
        float4 bb = *(const float4*)(b2 + lane * 4);
        float4 r;
        r.x = acc.x * inv + uv.x + bb.x;
        r.y = acc.y * inv + uv.y + bb.y;
        r.z = acc.z * inv + uv.z + bb.z;
        r.w = acc.w * inv + uv.w + bb.w;
        *(float4*)(out + (long long)gw * NCLS + lane * 4) = r;
    }
}

// ---------------------------------------------------------------------------
extern "C" void kernel_launch(void* const* d_in, const int* in_sizes, int n_in,
                              void* d_out, int out_size) {
    const float* x   = (const float*)d_in[0];
    const void*  ei  = d_in[1];
    const float* w1l = (const float*)d_in[2];
    const float* w1r = (const float*)d_in[3];
    const float* b1  = (const float*)d_in[4];
    const float* w2l = (const float*)d_in[5];
    const float* w2r = (const float*)d_in[6];
    const float* b2  = (const float*)d_in[7];
    float* out = (float*)d_out;

    int E = in_sizes[1] / 2;
    int N = in_sizes[0] / F;   // 50000

    float *pPT, *pH, *pWcat;
    int *pSrc, *pDst, *pCsr, *pCnt, *pFill, *pOffs, *pIncl, *pBsum, *pBexc;
    cudaGetSymbolAddress((void**)&pPT,   g_pt);
    cudaGetSymbolAddress((void**)&pH,    g_h);
    cudaGetSymbolAddress((void**)&pWcat, g_wcat);
    cudaGetSymbolAddress((void**)&pSrc,  g_src);
    cudaGetSymbolAddress((void**)&pDst,  g_dst);
    cudaGetSymbolAddress((void**)&pCsr,  g_csr);
    cudaGetSymbolAddress((void**)&pCnt,  g_cnt);
    cudaGetSymbolAddress((void**)&pFill, g_fill);
    cudaGetSymbolAddress((void**)&pOffs, g_offs);
    cudaGetSymbolAddress((void**)&pIncl, g_incl);
    cudaGetSymbolAddress((void**)&pBsum, g_bsum);
    cudaGetSymbolAddress((void**)&pBexc, g_bexc);

    const int T = 256;
    int gemm_rows = (N + 127) / 128;          // 391
    int edge_blocks = (E + T - 1) / T;        // 2344
    int warp_blocks = (N * 32 + T - 1) / T;   // 6250

    // --- graph preprocessing ---
    detect_kernel<<<1, 32>>>(ei);
    zero_int2_kernel<<<128, T>>>((int4*)pCnt, (int4*)pFill, NN / 4 + 1);
    build_wcat_kernel<<<(F * 256 + T - 1) / T, T>>>(w1l, w1r, pWcat);
    hist_kernel<<<edge_blocks, T>>>(ei, pSrc, pDst, pCnt, E);
    scan1_kernel<<<NSB, SCB>>>(pCnt, pIncl, pBsum);
    scan2_kernel<<<1, 128>>>(pBsum, pBexc);
    scan3_kernel<<<(NN + T - 1) / T, T>>>(pIncl, pCnt, pBexc, pOffs);
    fill_kernel<<<edge_blocks, T>>>(pSrc, pDst, pOffs, pFill, pCsr, E);

    // --- layer 1: pt = x @ [w1l | w1r], then fused agg+epilogue -> h ---
    gemm_kernel<2, 256, 256, 256><<<dim3(gemm_rows, 2), T>>>(x, pWcat, pPT, N);
    agg1_kernel<<<warp_blocks, T>>>(pCsr, pOffs, pCnt, pPT, b1, pH);

    // --- layer 2: q = h@w2l, u = h@w2r, fused agg+epilogue -> out ---
    float* pQ = pPT;                 // reuse (pt free after agg1)
    float* pU = pPT + (long long)NN * NCLS;
    gemm_kernel<1, NCLS, NCLS, NCLS><<<dim3(gemm_rows, 1), T>>>(pH, w2l, pQ, N);
    gemm_kernel<1, NCLS, NCLS, NCLS><<<dim3(gemm_rows, 1), T>>>(pH, w2r, pU, N);
    agg2_kernel<<<warp_blocks, T>>>(pCsr, pOffs, pCnt, pQ, pU, b2, out);
}

// round 5
// speedup vs baseline: 1.5886x; 1.0372x over previous
#include <cuda_runtime.h>
#include <cstdint>

#define NN   50000
#define F    128
#define NCLS 40
#define MAXE 600000
#define SCB  512
#define NSB  ((NN + SCB - 1) / SCB)   // 98

// ---------------- scratch (__device__ globals; no allocations) -------------
__device__ float g_pt[NN * 256];     // layer1: [p|t] (stride 256); layer2: [q|u] (stride 80)
__device__ float g_h[NN * F];        // hidden activations
__device__ float g_wcat[F * 256];    // [w1l | w1r]
__device__ float g_wcat2[F * 80];    // [w2l | w2r]
__device__ int g_src[MAXE], g_dst[MAXE], g_csr[MAXE];
__device__ int g_cnt[NN], g_offs[NN], g_incl[NN];
__device__ int g_bsum[NSB], g_bexc[NSB];
__device__ int g_mode32;

// ---------------------------------------------------------------------------
__global__ void detect_kernel(const void* ei) {
    if (threadIdx.x == 0 && blockIdx.x == 0) {
        const long long* p = (const long long*)ei;
        int m32 = 0;
        for (int i = 0; i < 16; i++) {
            long long v = p[i];
            if (v < 0 || v >= NN) { m32 = 1; break; }
        }
        g_mode32 = m32;
    }
}

__global__ void zero_int_kernel(int4* a, int n4) {
    int i = blockIdx.x * blockDim.x + threadIdx.x;
    int stride = gridDim.x * blockDim.x;
    int4 z = make_int4(0, 0, 0, 0);
    for (; i < n4; i += stride) a[i] = z;
}

// Build both concatenated weight matrices in one launch.
__global__ void build_wcat_kernel(const float* __restrict__ w1l,
                                  const float* __restrict__ w1r,
                                  const float* __restrict__ w2l,
                                  const float* __restrict__ w2r,
                                  float* __restrict__ wcat,
                                  float* __restrict__ wcat2) {
    int i = blockIdx.x * blockDim.x + threadIdx.x;
    if (i < F * 256) {
        int k = i >> 8, c = i & 255;
        wcat[i] = (c < 128) ? w1l[k * 128 + c] : w1r[k * 128 + (c - 128)];
    } else if (i < F * 256 + F * 80) {
        int j = i - F * 256;
        int k = j / 80, c = j % 80;
        wcat2[j] = (c < NCLS) ? w2l[k * NCLS + c] : w2r[k * NCLS + (c - NCLS)];
    }
}

// convert indices to int32 + histogram in-degree
__global__ void hist_kernel(const void* __restrict__ ei,
                            int* __restrict__ src32, int* __restrict__ dst32,
                            int* __restrict__ cnt, int E) {
    const int mode32 = g_mode32;
    int stride = gridDim.x * blockDim.x;
    for (int e = blockIdx.x * blockDim.x + threadIdx.x; e < E; e += stride) {
        int s, d;
        if (mode32) {
            const int* p = (const int*)ei;
            s = p[e]; d = p[E + e];
        } else {
            const long long* p = (const long long*)ei;
            s = (int)p[e]; d = (int)p[E + e];
        }
        src32[e] = s;
        dst32[e] = d;
        atomicAdd(&cnt[d], 1);
    }
}

// --------- 3-kernel exclusive scan of g_cnt -> g_offs ----------------------
__global__ void scan1_kernel(const int* __restrict__ cnt,
                             int* __restrict__ incl, int* __restrict__ bsum) {
    __shared__ int sm[SCB];
    int t = threadIdx.x;
    int i = blockIdx.x * SCB + t;
    int v = (i < NN) ? cnt[i] : 0;
    sm[t] = v;
    __syncthreads();
    for (int off = 1; off < SCB; off <<= 1) {
        int x = (t >= off) ? sm[t - off] : 0;
        __syncthreads();
        sm[t] += x;
        __syncthreads();
    }
    if (i < NN) incl[i] = sm[t];
    if (t == SCB - 1) bsum[blockIdx.x] = sm[t];
}

__global__ void scan2_kernel(const int* __restrict__ bsum, int* __restrict__ bexc) {
    __shared__ int sm[128];
    int t = threadIdx.x;
    int v = (t < NSB) ? bsum[t] : 0;
    sm[t] = v;
    __syncthreads();
    for (int off = 1; off < 128; off <<= 1) {
        int x = (t >= off) ? sm[t - off] : 0;
        __syncthreads();
        sm[t] += x;
        __syncthreads();
    }
    if (t < NSB) bexc[t] = sm[t] - v;   // exclusive
}

__global__ void scan3_kernel(const int* __restrict__ incl,
                             const int* __restrict__ cnt,
                             const int* __restrict__ bexc,
                             int* __restrict__ offs) {
    int i = blockIdx.x * blockDim.x + threadIdx.x;
    if (i < NN) offs[i] = incl[i] - cnt[i] + bexc[i >> 9];
}

// Fill CSR; bumps offs in place (post-fill: offs[n] = segment END).
__global__ void fill_kernel(const int* __restrict__ src32,
                            const int* __restrict__ dst32,
                            int* __restrict__ offs, int* __restrict__ csr, int E) {
    int stride = gridDim.x * blockDim.x;
    for (int e = blockIdx.x * blockDim.x + threadIdx.x; e < E; e += stride) {
        int d = dst32[e];
        int slot = atomicAdd(&offs[d], 1);
        csr[slot] = src32[e];
    }
}

// ---------------------------------------------------------------------------
// Double-buffered register-blocked SGEMM: C[N x ...] = A[N x 128] @ B
// BM=128, BK=8, 256 threads, 2-stage smem ping-pong, 1 sync per k-tile.
// HALVES: 64-col sub-blocks. SWB/SWC: row strides. NCV: valid cols.
template <int HALVES, int SWB, int SWC, int NCV>
__global__ __launch_bounds__(256, 2)
void gemm_kernel(const float* __restrict__ A,
                 const float* __restrict__ B,
                 float* __restrict__ C,
                 int Nrows) {
    constexpr int BM = 128, BK = 8, NT = F / BK;   // 16 k-tiles
    __shared__ float As[2][BK][BM + 4];
    __shared__ float Bs[2][BK][64 * HALVES];

    int tid = threadIdx.x;
    int tx = tid & 15;
    int ty = tid >> 4;
    int brow = blockIdx.x * BM;
    int colbase = blockIdx.y * 128;

    int ar = tid >> 1;
    int ak4 = (tid & 1) * 4;
    bool a_valid = (brow + ar) < Nrows;
    const float* a_ptr = A + (long long)(brow + ar) * F + ak4;

    int bk, bc4;
    bool b_act;
    if (HALVES == 2) { bk = tid >> 5; bc4 = (tid & 31) * 4; b_act = true; }
    else             { bk = tid >> 4; bc4 = (tid & 15) * 4; b_act = (tid < 128); }
    bool b_valid = b_act && (colbase + bc4 < NCV);
    const float* b_ptr = B + (long long)bk * SWB + colbase + bc4;

    // prologue: tile 0 -> buffer 0
    {
        float4 av = make_float4(0.f, 0.f, 0.f, 0.f);
        if (a_valid) av = *(const float4*)(a_ptr);
        As[0][ak4 + 0][ar] = av.x;
        As[0][ak4 + 1][ar] = av.y;
        As[0][ak4 + 2][ar] = av.z;
        As[0][ak4 + 3][ar] = av.w;
        if (b_act) {
            float4 bv = make_float4(0.f, 0.f, 0.f, 0.f);
            if (b_valid) bv = *(const float4*)(b_ptr);
            *(float4*)&Bs[0][bk][bc4] = bv;
        }
    }
    __syncthreads();

    float acc[2][HALVES][4][4];
#pragma unroll
    for (int rh = 0; rh < 2; rh++)
#pragma unroll
        for (int ch = 0; ch < HALVES; ch++)
#pragma unroll
            for (int i = 0; i < 4; i++)
#pragma unroll
                for (int j = 0; j < 4; j++) acc[rh][ch][i][j] = 0.0f;

    for (int kt = 0; kt < NT; kt++) {
        int cur = kt & 1;
        float4 av_n = make_float4(0.f, 0.f, 0.f, 0.f);
        float4 bv_n = make_float4(0.f, 0.f, 0.f, 0.f);
        if (kt + 1 < NT) {
            if (a_valid) av_n = *(const float4*)(a_ptr + (kt + 1) * BK);
            if (b_valid) bv_n = *(const float4*)(b_ptr + (long long)(kt + 1) * BK * SWB);
        }
#pragma unroll
        for (int kk = 0; kk < BK; kk++) {
            float4 a0 = *(const float4*)&As[cur][kk][ty * 4];
            float4 a1 = *(const float4*)&As[cur][kk][64 + ty * 4];
            float ar_[2][4] = {{a0.x, a0.y, a0.z, a0.w}, {a1.x, a1.y, a1.z, a1.w}};
            float bc_[HALVES][4];
            float4 b0 = *(const float4*)&Bs[cur][kk][tx * 4];
            bc_[0][0] = b0.x; bc_[0][1] = b0.y; bc_[0][2] = b0.z; bc_[0][3] = b0.w;
            if (HALVES == 2) {
                float4 b1 = *(const float4*)&Bs[cur][kk][64 + tx * 4];
                bc_[1][0] = b1.x; bc_[1][1] = b1.y; bc_[1][2] = b1.z; bc_[1][3] = b1.w;
            }
#pragma unroll
            for (int rh = 0; rh < 2; rh++)
#pragma unroll
                for (int ch = 0; ch < HALVES; ch++)
#pragma unroll
                    for (int i = 0; i < 4; i++)
#pragma unroll
                        for (int j = 0; j < 4; j++)
                            acc[rh][ch][i][j] += ar_[rh][i] * bc_[ch][j];
        }
        if (kt + 1 < NT) {
            int nxt = 1 - cur;
            As[nxt][ak4 + 0][ar] = av_n.x;
            As[nxt][ak4 + 1][ar] = av_n.y;
            As[nxt][ak4 + 2][ar] = av_n.z;
            As[nxt][ak4 + 3][ar] = av_n.w;
            if (b_act) *(float4*)&Bs[nxt][bk][bc4] = bv_n;
            __syncthreads();
        }
    }

#pragma unroll
    for (int rh = 0; rh < 2; rh++) {
#pragma unroll
        for (int i = 0; i < 4; i++) {
            int row = brow + rh * 64 + ty * 4 + i;
            if (row >= Nrows) continue;
#pragma unroll
            for (int ch = 0; ch < HALVES; ch++) {
                int col = colbase + ch * 64 + tx * 4;
                if (col >= NCV) continue;
                float4 v;
                v.x = acc[rh][ch][i][0];
                v.y = acc[rh][ch][i][1];
                v.z = acc[rh][ch][i][2];
                v.w = acc[rh][ch][i][3];
                *(float4*)(C + (long long)row * SWC + col) = v;
            }
        }
    }
}

// ---------------------------------------------------------------------------
// Layer-1 aggregation + epilogue: h[n] = relu(mean_{s in N(n)} p[s] + t[n] + b1)
// pt stride 256: p = cols 0:128, t = cols 128:256. Warp per node, post-fill
// offs[n] is the segment END -> beg = offs[n] - cnt[n].
__global__ void agg1_kernel(const int* __restrict__ csr,
                            const int* __restrict__ offs,
                            const int* __restrict__ cnt,
                            const float* __restrict__ pt,
                            const float* __restrict__ b1,
                            float* __restrict__ h) {
    int gw = (blockIdx.x * blockDim.x + threadIdx.x) >> 5;
    int lane = threadIdx.x & 31;
    if (gw >= NN) return;
    int dg = cnt[gw];
    int beg = offs[gw] - dg;
    float4 acc0 = make_float4(0.f, 0.f, 0.f, 0.f);
    float4 acc1 = make_float4(0.f, 0.f, 0.f, 0.f);
    int i = 0;
    for (; i + 4 <= dg; i += 4) {
        int s0 = __ldg(&csr[beg + i]);
        int s1 = __ldg(&csr[beg + i + 1]);
        int s2 = __ldg(&csr[beg + i + 2]);
        int s3 = __ldg(&csr[beg + i + 3]);
        float4 v0 = *(const float4*)(pt + (long long)s0 * 256 + lane * 4);
        float4 v1 = *(const float4*)(pt + (long long)s1 * 256 + lane * 4);
        float4 v2 = *(const float4*)(pt + (long long)s2 * 256 + lane * 4);
        float4 v3 = *(const float4*)(pt + (long long)s3 * 256 + lane * 4);
        acc0.x += v0.x + v1.x; acc0.y += v0.y + v1.y;
        acc0.z += v0.z + v1.z; acc0.w += v0.w + v1.w;
        acc1.x += v2.x + v3.x; acc1.y += v2.y + v3.y;
        acc1.z += v2.z + v3.z; acc1.w += v2.w + v3.w;
    }
    for (; i < dg; i++) {
        int s = __ldg(&csr[beg + i]);
        float4 v = *(const float4*)(pt + (long long)s * 256 + lane * 4);
        acc0.x += v.x; acc0.y += v.y; acc0.z += v.z; acc0.w += v.w;
    }
    float inv = 1.0f / fmaxf((float)dg, 1.0f);
    float4 t = *(const float4*)(pt + (long long)gw * 256 + 128 + lane * 4);
    float4 bb = *(const float4*)(b1 + lane * 4);
    float4 r;
    r.x = fmaxf((acc0.x + acc1.x) * inv + t.x + bb.x, 0.f);
    r.y = fmaxf((acc0.y + acc1.y) * inv + t.y + bb.y, 0.f);
    r.z = fmaxf((acc0.z + acc1.z) * inv + t.z + bb.z, 0.f);
    r.w = fmaxf((acc0.w + acc1.w) * inv + t.w + bb.w, 0.f);
    *(float4*)(h + (long long)gw * F + lane * 4) = r;
}

// Layer-2: out[n] = mean q[s] + u[n] + b2. qu stride 80: q=0:40, u=40:80.
__global__ void agg2_kernel(const int* __restrict__ csr,
                            const int* __restrict__ offs,
                            const int* __restrict__ cnt,
                            const float* __restrict__ qu,
                            const float* __restrict__ b2,
                            float* __restrict__ out) {
    int gw = (blockIdx.x * blockDim.x + threadIdx.x) >> 5;
    int lane = threadIdx.x & 31;
    if (gw >= NN) return;
    int dg = cnt[gw];
    int beg = offs[gw] - dg;
    if (lane < 10) {
        float4 acc0 = make_float4(0.f, 0.f, 0.f, 0.f);
        float4 acc1 = make_float4(0.f, 0.f, 0.f, 0.f);
        int i = 0;
        for (; i + 4 <= dg; i += 4) {
            int s0 = __ldg(&csr[beg + i]);
            int s1 = __ldg(&csr[beg + i + 1]);
            int s2 = __ldg(&csr[beg + i + 2]);
            int s3 = __ldg(&csr[beg + i + 3]);
            float4 v0 = *(const float4*)(qu + (long long)s0 * 80 + lane * 4);
            float4 v1 = *(const float4*)(qu + (long long)s1 * 80 + lane * 4);
            float4 v2 = *(const float4*)(qu + (long long)s2 * 80 + lane * 4);
            float4 v3 = *(const float4*)(qu + (long long)s3 * 80 + lane * 4);
            acc0.x += v0.x + v1.x; acc0.y += v0.y + v1.y;
            acc0.z += v0.z + v1.z; acc0.w += v0.w + v1.w;
            acc1.x += v2.x + v3.x; acc1.y += v2.y + v3.y;
            acc1.z += v2.z + v3.z; acc1.w += v2.w + v3.w;
        }
        for (; i < dg; i++) {
            int s = __ldg(&csr[beg + i]);
            float4 v = *(const float4*)(qu + (long long)s * 80 + lane * 4);
            acc0.x += v.x; acc0.y += v.y; acc0.z += v.z; acc0.w += v.w;
        }
        float inv = 1.0f / fmaxf((float)dg, 1.0f);
        float4 uv = *(const float4*)(qu + (long long)gw * 80 + NCLS + lane * 4);
        float4 bb = *(const float4*)(b2 + lane * 4);
        float4 r;
        r.x = (acc0.x + acc1.x) * inv + uv.x + bb.x;
        r.y = (acc0.y + acc1.y) * inv + uv.y + bb.y;
        r.z = (acc0.z + acc1.z) * inv + uv.z + bb.z;
        r.w = (acc0.w + acc1.w) * inv + uv.w + bb.w;
        *(float4*)(out + (long long)gw * NCLS + lane * 4) = r;
    }
}

// ---------------------------------------------------------------------------
extern "C" void kernel_launch(void* const* d_in, const int* in_sizes, int n_in,
                              void* d_out, int out_size) {
    const float* x   = (const float*)d_in[0];
    const void*  ei  = d_in[1];
    const float* w1l = (const float*)d_in[2];
    const float* w1r = (const float*)d_in[3];
    const float* b1  = (const float*)d_in[4];
    const float* w2l = (const float*)d_in[5];
    const float* w2r = (const float*)d_in[6];
    const float* b2  = (const float*)d_in[7];
    float* out = (float*)d_out;

    int E = in_sizes[1] / 2;
    int N = in_sizes[0] / F;   // 50000

    float *pPT, *pH, *pWcat, *pWcat2;
    int *pSrc, *pDst, *pCsr, *pCnt, *pOffs, *pIncl, *pBsum, *pBexc;
    cudaGetSymbolAddress((void**)&pPT,    g_pt);
    cudaGetSymbolAddress((void**)&pH,     g_h);
    cudaGetSymbolAddress((void**)&pWcat,  g_wcat);
    cudaGetSymbolAddress((void**)&pWcat2, g_wcat2);
    cudaGetSymbolAddress((void**)&pSrc,   g_src);
    cudaGetSymbolAddress((void**)&pDst,   g_dst);
    cudaGetSymbolAddress((void**)&pCsr,   g_csr);
    cudaGetSymbolAddress((void**)&pCnt,   g_cnt);
    cudaGetSymbolAddress((void**)&pOffs,  g_offs);
    cudaGetSymbolAddress((void**)&pIncl,  g_incl);
    cudaGetSymbolAddress((void**)&pBsum,  g_bsum);
    cudaGetSymbolAddress((void**)&pBexc,  g_bexc);

    const int T = 256;
    int gemm_rows = (N + 127) / 128;          // 391
    int edge_blocks = (E + T - 1) / T;        // 2344
    int warp_blocks = (N * 32 + T - 1) / T;   // 6250

    // 1: detect edge dtype
    detect_kernel<<<1, 32>>>(ei);
    // 2: zero histogram
    zero_int_kernel<<<64, T>>>((int4*)pCnt, NN / 4 + 1);
    // 3: build concatenated weights
    build_wcat_kernel<<<(F * 256 + F * 80 + T - 1) / T, T>>>(
        w1l, w1r, w2l, w2r, pWcat, pWcat2);
    // 4: indices -> int32 + degree histogram
    hist_kernel<<<edge_blocks, T>>>(ei, pSrc, pDst, pCnt, E);
    // 5: scan stage 1
    scan1_kernel<<<NSB, SCB>>>(pCnt, pIncl, pBsum);
    // 6: layer-1 GEMM (profiled launch under -s 5 -c 1)
    gemm_kernel<2, 256, 256, 256><<<dim3(gemm_rows, 2), T>>>(x, pWcat, pPT, N);
    // 7-9: finish CSR
    scan2_kernel<<<1, 128>>>(pBsum, pBexc);
    scan3_kernel<<<(NN + T - 1) / T, T>>>(pIncl, pCnt, pBexc, pOffs);
    fill_kernel<<<edge_blocks, T>>>(pSrc, pDst, pOffs, pCsr, E);
    // 10: layer-1 aggregation + epilogue -> h
    agg1_kernel<<<warp_blocks, T>>>(pCsr, pOffs, pCnt, pPT, b1, pH);
    // 11: layer-2 fused GEMM  qu = h @ [w2l|w2r]
    gemm_kernel<2, 80, 80, 80><<<dim3(gemm_rows, 1), T>>>(pH, pWcat2, pPT, N);
    // 12: layer-2 aggregation + epilogue -> out
    agg2_kernel<<<warp_blocks, T>>>(pCsr, pOffs, pCnt, pPT, b2, out);
}

// round 6
// speedup vs baseline: 1.7344x; 1.0918x over previous
#include <cuda_runtime.h>
#include <cstdint>

#define NN   50000
#define F    128
#define NCLS 40
#define MAXE 600000
#define SCB  512
#define NSB  ((NN + SCB - 1) / SCB)   // 98

// ---------------- scratch (__device__ globals; no allocations) -------------
__device__ float g_pt[NN * 256];     // layer1: [p|t] (stride 256); layer2: [q|u] (stride 80)
__device__ float g_h[NN * F];        // hidden activations
__device__ float g_wcat[F * 256];    // [w1l | w1r]
__device__ float g_wcat2[F * 80];    // [w2l | w2r]
__device__ int g_src[MAXE], g_dst[MAXE], g_csr[MAXE];
__device__ int g_cnt[NN], g_offs[NN], g_incl[NN];
__device__ int g_bsum[NSB], g_bexc[NSB];
__device__ int g_mode32;

// ---------------------------------------------------------------------------
__global__ void detect_kernel(const void* ei) {
    if (threadIdx.x == 0 && blockIdx.x == 0) {
        const long long* p = (const long long*)ei;
        int m32 = 0;
        for (int i = 0; i < 16; i++) {
            long long v = p[i];
            if (v < 0 || v >= NN) { m32 = 1; break; }
        }
        g_mode32 = m32;
    }
}

__global__ void zero_int_kernel(int4* a, int n4) {
    int i = blockIdx.x * blockDim.x + threadIdx.x;
    int stride = gridDim.x * blockDim.x;
    int4 z = make_int4(0, 0, 0, 0);
    for (; i < n4; i += stride) a[i] = z;
}

// Build both concatenated weight matrices in one launch.
__global__ void build_wcat_kernel(const float* __restrict__ w1l,
                                  const float* __restrict__ w1r,
                                  const float* __restrict__ w2l,
                                  const float* __restrict__ w2r,
                                  float* __restrict__ wcat,
                                  float* __restrict__ wcat2) {
    int i = blockIdx.x * blockDim.x + threadIdx.x;
    if (i < F * 256) {
        int k = i >> 8, c = i & 255;
        wcat[i] = (c < 128) ? w1l[k * 128 + c] : w1r[k * 128 + (c - 128)];
    } else if (i < F * 256 + F * 80) {
        int j = i - F * 256;
        int k = j / 80, c = j % 80;
        wcat2[j] = (c < NCLS) ? w2l[k * NCLS + c] : w2r[k * NCLS + (c - NCLS)];
    }
}

// convert indices to int32 + histogram in-degree
__global__ void hist_kernel(const void* __restrict__ ei,
                            int* __restrict__ src32, int* __restrict__ dst32,
                            int* __restrict__ cnt, int E) {
    const int mode32 = g_mode32;
    int stride = gridDim.x * blockDim.x;
    for (int e = blockIdx.x * blockDim.x + threadIdx.x; e < E; e += stride) {
        int s, d;
        if (mode32) {
            const int* p = (const int*)ei;
            s = p[e]; d = p[E + e];
        } else {
            const long long* p = (const long long*)ei;
            s = (int)p[e]; d = (int)p[E + e];
        }
        src32[e] = s;
        dst32[e] = d;
        atomicAdd(&cnt[d], 1);
    }
}

// --------- 3-kernel exclusive scan of g_cnt -> g_offs ----------------------
__global__ void scan1_kernel(const int* __restrict__ cnt,
                             int* __restrict__ incl, int* __restrict__ bsum) {
    __shared__ int sm[SCB];
    int t = threadIdx.x;
    int i = blockIdx.x * SCB + t;
    int v = (i < NN) ? cnt[i] : 0;
    sm[t] = v;
    __syncthreads();
    for (int off = 1; off < SCB; off <<= 1) {
        int x = (t >= off) ? sm[t - off] : 0;
        __syncthreads();
        sm[t] += x;
        __syncthreads();
    }
    if (i < NN) incl[i] = sm[t];
    if (t == SCB - 1) bsum[blockIdx.x] = sm[t];
}

__global__ void scan2_kernel(const int* __restrict__ bsum, int* __restrict__ bexc) {
    __shared__ int sm[128];
    int t = threadIdx.x;
    int v = (t < NSB) ? bsum[t] : 0;
    sm[t] = v;
    __syncthreads();
    for (int off = 1; off < 128; off <<= 1) {
        int x = (t >= off) ? sm[t - off] : 0;
        __syncthreads();
        sm[t] += x;
        __syncthreads();
    }
    if (t < NSB) bexc[t] = sm[t] - v;   // exclusive
}

__global__ void scan3_kernel(const int* __restrict__ incl,
                             const int* __restrict__ cnt,
                             const int* __restrict__ bexc,
                             int* __restrict__ offs) {
    int i = blockIdx.x * blockDim.x + threadIdx.x;
    if (i < NN) offs[i] = incl[i] - cnt[i] + bexc[i >> 9];
}

// Fill CSR; bumps offs in place (post-fill: offs[n] = segment END).
__global__ void fill_kernel(const int* __restrict__ src32,
                            const int* __restrict__ dst32,
                            int* __restrict__ offs, int* __restrict__ csr, int E) {
    int stride = gridDim.x * blockDim.x;
    for (int e = blockIdx.x * blockDim.x + threadIdx.x; e < E; e += stride) {
        int d = dst32[e];
        int slot = atomicAdd(&offs[d], 1);
        csr[slot] = src32[e];
    }
}

// ---------------------------------------------------------------------------
// Double-buffered register-blocked SGEMM: C[N x ...] = A[N x 128] @ B
// BM=128, BK=8, 256 threads, 2-stage smem ping-pong, 1 sync per k-tile.
// HALVES: 64-col sub-blocks. SWB/SWC: row strides. NCV: valid cols.
template <int HALVES, int SWB, int SWC, int NCV>
__global__ __launch_bounds__(256, 2)
void gemm_kernel(const float* __restrict__ A,
                 const float* __restrict__ B,
                 float* __restrict__ C,
                 int Nrows) {
    constexpr int BM = 128, BK = 8, NT = F / BK;   // 16 k-tiles
    __shared__ float As[2][BK][BM + 4];
    __shared__ float Bs[2][BK][64 * HALVES];

    int tid = threadIdx.x;
    int tx = tid & 15;
    int ty = tid >> 4;
    int brow = blockIdx.x * BM;
    int colbase = blockIdx.y * 128;

    int ar = tid >> 1;
    int ak4 = (tid & 1) * 4;
    bool a_valid = (brow + ar) < Nrows;
    const float* a_ptr = A + (long long)(brow + ar) * F + ak4;

    int bk, bc4;
    bool b_act;
    if (HALVES == 2) { bk = tid >> 5; bc4 = (tid & 31) * 4; b_act = true; }
    else             { bk = tid >> 4; bc4 = (tid & 15) * 4; b_act = (tid < 128); }
    bool b_valid = b_act && (colbase + bc4 < NCV);
    const float* b_ptr = B + (long long)bk * SWB + colbase + bc4;

    // prologue: tile 0 -> buffer 0
    {
        float4 av = make_float4(0.f, 0.f, 0.f, 0.f);
        if (a_valid) av = *(const float4*)(a_ptr);
        As[0][ak4 + 0][ar] = av.x;
        As[0][ak4 + 1][ar] = av.y;
        As[0][ak4 + 2][ar] = av.z;
        As[0][ak4 + 3][ar] = av.w;
        if (b_act) {
            float4 bv = make_float4(0.f, 0.f, 0.f, 0.f);
            if (b_valid) bv = *(const float4*)(b_ptr);
            *(float4*)&Bs[0][bk][bc4] = bv;
        }
    }
    __syncthreads();

    float acc[2][HALVES][4][4];
#pragma unroll
    for (int rh = 0; rh < 2; rh++)
#pragma unroll
        for (int ch = 0; ch < HALVES; ch++)
#pragma unroll
            for (int i = 0; i < 4; i++)
#pragma unroll
                for (int j = 0; j < 4; j++) acc[rh][ch][i][j] = 0.0f;

    for (int kt = 0; kt < NT; kt++) {
        int cur = kt & 1;
        float4 av_n = make_float4(0.f, 0.f, 0.f, 0.f);
        float4 bv_n = make_float4(0.f, 0.f, 0.f, 0.f);
        if (kt + 1 < NT) {
            if (a_valid) av_n = *(const float4*)(a_ptr + (kt + 1) * BK);
            if (b_valid) bv_n = *(const float4*)(b_ptr + (long long)(kt + 1) * BK * SWB);
        }
#pragma unroll
        for (int kk = 0; kk < BK; kk++) {
            float4 a0 = *(const float4*)&As[cur][kk][ty * 4];
            float4 a1 = *(const float4*)&As[cur][kk][64 + ty * 4];
            float ar_[2][4] = {{a0.x, a0.y, a0.z, a0.w}, {a1.x, a1.y, a1.z, a1.w}};
            float bc_[HALVES][4];
            float4 b0 = *(const float4*)&Bs[cur][kk][tx * 4];
            bc_[0][0] = b0.x; bc_[0][1] = b0.y; bc_[0][2] = b0.z; bc_[0][3] = b0.w;
            if (HALVES == 2) {
                float4 b1 = *(const float4*)&Bs[cur][kk][64 + tx * 4];
                bc_[1][0] = b1.x; bc_[1][1] = b1.y; bc_[1][2] = b1.z; bc_[1][3] = b1.w;
            }
#pragma unroll
            for (int rh = 0; rh < 2; rh++)
#pragma unroll
                for (int ch = 0; ch < HALVES; ch++)
#pragma unroll
                    for (int i = 0; i < 4; i++)
#pragma unroll
                        for (int j = 0; j < 4; j++)
                            acc[rh][ch][i][j] += ar_[rh][i] * bc_[ch][j];
        }
        if (kt + 1 < NT) {
            int nxt = 1 - cur;
            As[nxt][ak4 + 0][ar] = av_n.x;
            As[nxt][ak4 + 1][ar] = av_n.y;
            As[nxt][ak4 + 2][ar] = av_n.z;
            As[nxt][ak4 + 3][ar] = av_n.w;
            if (b_act) *(float4*)&Bs[nxt][bk][bc4] = bv_n;
            __syncthreads();
        }
    }

#pragma unroll
    for (int rh = 0; rh < 2; rh++) {
#pragma unroll
        for (int i = 0; i < 4; i++) {
            int row = brow + rh * 64 + ty * 4 + i;
            if (row >= Nrows) continue;
#pragma unroll
            for (int ch = 0; ch < HALVES; ch++) {
                int col = colbase + ch * 64 + tx * 4;
                if (col >= NCV) continue;
                float4 v;
                v.x = acc[rh][ch][i][0];
                v.y = acc[rh][ch][i][1];
                v.z = acc[rh][ch][i][2];
                v.w = acc[rh][ch][i][3];
                *(float4*)(C + (long long)row * SWC + col) = v;
            }
        }
    }
}

// ---------------------------------------------------------------------------
// Layer-1 aggregation + epilogue: h[n] = relu(mean_{s in N(n)} p[s] + t[n] + b1)
__global__ void agg1_kernel(const int* __restrict__ csr,
                            const int* __restrict__ offs,
                            const int* __restrict__ cnt,
                            const float* __restrict__ pt,
                            const float* __restrict__ b1,
                            float* __restrict__ h) {
    int gw = (blockIdx.x * blockDim.x + threadIdx.x) >> 5;
    int lane = threadIdx.x & 31;
    if (gw >= NN) return;
    int dg = cnt[gw];
    int beg = offs[gw] - dg;
    float4 acc0 = make_float4(0.f, 0.f, 0.f, 0.f);
    float4 acc1 = make_float4(0.f, 0.f, 0.f, 0.f);
    int i = 0;
    for (; i + 4 <= dg; i += 4) {
        int s0 = __ldg(&csr[beg + i]);
        int s1 = __ldg(&csr[beg + i + 1]);
        int s2 = __ldg(&csr[beg + i + 2]);
        int s3 = __ldg(&csr[beg + i + 3]);
        float4 v0 = *(const float4*)(pt + (long long)s0 * 256 + lane * 4);
        float4 v1 = *(const float4*)(pt + (long long)s1 * 256 + lane * 4);
        float4 v2 = *(const float4*)(pt + (long long)s2 * 256 + lane * 4);
        float4 v3 = *(const float4*)(pt + (long long)s3 * 256 + lane * 4);
        acc0.x += v0.x + v1.x; acc0.y += v0.y + v1.y;
        acc0.z += v0.z + v1.z; acc0.w += v0.w + v1.w;
        acc1.x += v2.x + v3.x; acc1.y += v2.y + v3.y;
        acc1.z += v2.z + v3.z; acc1.w += v2.w + v3.w;
    }
    for (; i < dg; i++) {
        int s = __ldg(&csr[beg + i]);
        float4 v = *(const float4*)(pt + (long long)s * 256 + lane * 4);
        acc0.x += v.x; acc0.y += v.y; acc0.z += v.z; acc0.w += v.w;
    }
    float inv = 1.0f / fmaxf((float)dg, 1.0f);
    float4 t = *(const float4*)(pt + (long long)gw * 256 + 128 + lane * 4);
    float4 bb = *(const float4*)(b1 + lane * 4);
    float4 r;
    r.x = fmaxf((acc0.x + acc1.x) * inv + t.x + bb.x, 0.f);
    r.y = fmaxf((acc0.y + acc1.y) * inv + t.y + bb.y, 0.f);
    r.z = fmaxf((acc0.z + acc1.z) * inv + t.z + bb.z, 0.f);
    r.w = fmaxf((acc0.w + acc1.w) * inv + t.w + bb.w, 0.f);
    *(float4*)(h + (long long)gw * F + lane * 4) = r;
}

// Layer-2: out[n] = mean q[s] + u[n] + b2. qu stride 80: q=0:40, u=40:80.
__global__ void agg2_kernel(const int* __restrict__ csr,
                            const int* __restrict__ offs,
                            const int* __restrict__ cnt,
                            const float* __restrict__ qu,
                            const float* __restrict__ b2,
                            float* __restrict__ out) {
    int gw = (blockIdx.x * blockDim.x + threadIdx.x) >> 5;
    int lane = threadIdx.x & 31;
    if (gw >= NN) return;
    int dg = cnt[gw];
    int beg = offs[gw] - dg;
    if (lane < 10) {
        float4 acc0 = make_float4(0.f, 0.f, 0.f, 0.f);
        float4 acc1 = make_float4(0.f, 0.f, 0.f, 0.f);
        int i = 0;
        for (; i + 4 <= dg; i += 4) {
            int s0 = __ldg(&csr[beg + i]);
            int s1 = __ldg(&csr[beg + i + 1]);
            int s2 = __ldg(&csr[beg + i + 2]);
            int s3 = __ldg(&csr[beg + i + 3]);
            float4 v0 = *(const float4*)(qu + (long long)s0 * 80 + lane * 4);
            float4 v1 = *(const float4*)(qu + (long long)s1 * 80 + lane * 4);
            float4 v2 = *(const float4*)(qu + (long long)s2 * 80 + lane * 4);
            float4 v3 = *(const float4*)(qu + (long long)s3 * 80 + lane * 4);
            acc0.x += v0.x + v1.x; acc0.y += v0.y + v1.y;
            acc0.z += v0.z + v1.z; acc0.w += v0.w + v1.w;
            acc1.x += v2.x + v3.x; acc1.y += v2.y + v3.y;
            acc1.z += v2.z + v3.z; acc1.w += v2.w + v3.w;
        }
        for (; i < dg; i++) {
            int s = __ldg(&csr[beg + i]);
            float4 v = *(const float4*)(qu + (long long)s * 80 + lane * 4);
            acc0.x += v.x; acc0.y += v.y; acc0.z += v.z; acc0.w += v.w;
        }
        float inv = 1.0f / fmaxf((float)dg, 1.0f);
        float4 uv = *(const float4*)(qu + (long long)gw * 80 + NCLS + lane * 4);
        float4 bb = *(const float4*)(b2 + lane * 4);
        float4 r;
        r.x = (acc0.x + acc1.x) * inv + uv.x + bb.x;
        r.y = (acc0.y + acc1.y) * inv + uv.y + bb.y;
        r.z = (acc0.z + acc1.z) * inv + uv.z + bb.z;
        r.w = (acc0.w + acc1.w) * inv + uv.w + bb.w;
        *(float4*)(out + (long long)gw * NCLS + lane * 4) = r;
    }
}

// ---------------------------------------------------------------------------
extern "C" void kernel_launch(void* const* d_in, const int* in_sizes, int n_in,
                              void* d_out, int out_size) {
    const float* x   = (const float*)d_in[0];
    const void*  ei  = d_in[1];
    const float* w1l = (const float*)d_in[2];
    const float* w1r = (const float*)d_in[3];
    const float* b1  = (const float*)d_in[4];
    const float* w2l = (const float*)d_in[5];
    const float* w2r = (const float*)d_in[6];
    const float* b2  = (const float*)d_in[7];
    float* out = (float*)d_out;

    int E = in_sizes[1] / 2;
    int N = in_sizes[0] / F;   // 50000

    float *pPT, *pH, *pWcat, *pWcat2;
    int *pSrc, *pDst, *pCsr, *pCnt, *pOffs, *pIncl, *pBsum, *pBexc;
    cudaGetSymbolAddress((void**)&pPT,    g_pt);
    cudaGetSymbolAddress((void**)&pH,     g_h);
    cudaGetSymbolAddress((void**)&pWcat,  g_wcat);
    cudaGetSymbolAddress((void**)&pWcat2, g_wcat2);
    cudaGetSymbolAddress((void**)&pSrc,   g_src);
    cudaGetSymbolAddress((void**)&pDst,   g_dst);
    cudaGetSymbolAddress((void**)&pCsr,   g_csr);
    cudaGetSymbolAddress((void**)&pCnt,   g_cnt);
    cudaGetSymbolAddress((void**)&pOffs,  g_offs);
    cudaGetSymbolAddress((void**)&pIncl,  g_incl);
    cudaGetSymbolAddress((void**)&pBsum,  g_bsum);
    cudaGetSymbolAddress((void**)&pBexc,  g_bexc);

    const int T = 256;
    int gemm_rows = (N + 127) / 128;          // 391
    int edge_blocks = (E + T - 1) / T;        // 2344
    int warp_blocks = (N * 32 + T - 1) / T;   // 6250

    // Fork-join resources (created per call; harness only graph-replays, so
    // this host-side cost is outside the timed region; not destroyed to avoid
    // invalidating an active capture).
    cudaStream_t s2 = 0;
    cudaEvent_t eA = 0, eB = 0;
    bool forked = (cudaStreamCreateWithFlags(&s2, cudaStreamNonBlocking) == cudaSuccess);
    if (forked) forked = (cudaEventCreateWithFlags(&eA, cudaEventDisableTiming) == cudaSuccess);
    if (forked) forked = (cudaEventCreateWithFlags(&eB, cudaEventDisableTiming) == cudaSuccess);
    cudaStream_t sb = forked ? s2 : (cudaStream_t)0;   // branch stream

    // --- main stream: 1 detect, 2 zero, 3 wcat ---
    detect_kernel<<<1, 32>>>(ei);
    zero_int_kernel<<<64, T>>>((int4*)pCnt, NN / 4 + 1);
    build_wcat_kernel<<<(F * 256 + F * 80 + T - 1) / T, T>>>(
        w1l, w1r, w2l, w2r, pWcat, pWcat2);

    // fork
    if (forked) {
        cudaEventRecord(eA, 0);
        cudaStreamWaitEvent(s2, eA, 0);
    }

    // 4: layer-1 GEMM on main stream (4th launch -> profiled)
    gemm_kernel<2, 256, 256, 256><<<dim3(gemm_rows, 2), T>>>(x, pWcat, pPT, N);

    // CSR chain on branch stream (overlaps gemm1)
    hist_kernel<<<edge_blocks, T, 0, sb>>>(ei, pSrc, pDst, pCnt, E);
    scan1_kernel<<<NSB, SCB, 0, sb>>>(pCnt, pIncl, pBsum);
    scan2_kernel<<<1, 128, 0, sb>>>(pBsum, pBexc);
    scan3_kernel<<<(NN + T - 1) / T, T, 0, sb>>>(pIncl, pCnt, pBexc, pOffs);
    fill_kernel<<<edge_blocks, T, 0, sb>>>(pSrc, pDst, pOffs, pCsr, E);

    // join
    if (forked) {
        cudaEventRecord(eB, s2);
        cudaStreamWaitEvent((cudaStream_t)0, eB, 0);
    }

    // layer-1 aggregation + epilogue -> h
    agg1_kernel<<<warp_blocks, T>>>(pCsr, pOffs, pCnt, pPT, b1, pH);
    // layer-2 fused GEMM  qu = h @ [w2l|w2r]
    gemm_kernel<2, 80, 80, 80><<<dim3(gemm_rows, 1), T>>>(pH, pWcat2, pPT, N);
    // layer-2 aggregation + epilogue -> out
    agg2_kernel<<<warp_blocks, T>>>(pCsr, pOffs, pCnt, pPT, b2, out);
}

// round 7
// speedup vs baseline: 1.7942x; 1.0345x over previous
#include <cuda_runtime.h>
#include <cstdint>

#define NN   50000
#define F    128
#define NCLS 40
#define MAXE 600000
#define SCB  512
#define NSB  ((NN + SCB - 1) / SCB)   // 98

// ---------------- scratch (__device__ globals; no allocations) -------------
__device__ float g_pt[NN * 256];     // layer1: [p|t] (stride 256); layer2: [q|u] (stride 80)
__device__ float g_h[NN * F];        // hidden activations
__device__ float g_wcat[F * 256];    // [w1l | w1r]
__device__ float g_wcat2[F * 80];    // [w2l | w2r]
__device__ int g_src[MAXE], g_dst[MAXE], g_csr[MAXE];
__device__ int g_cnt[NN], g_offs[NN], g_incl[NN];
__device__ int g_bsum[NSB], g_bexc[NSB];
__device__ int g_mode32;

// ---------------------------------------------------------------------------
__global__ void detect_kernel(const void* ei) {
    if (threadIdx.x == 0 && blockIdx.x == 0) {
        const long long* p = (const long long*)ei;
        int m32 = 0;
        for (int i = 0; i < 16; i++) {
            long long v = p[i];
            if (v < 0 || v >= NN) { m32 = 1; break; }
        }
        g_mode32 = m32;
    }
}

__global__ void zero_int_kernel(int4* a, int n4) {
    int i = blockIdx.x * blockDim.x + threadIdx.x;
    int stride = gridDim.x * blockDim.x;
    int4 z = make_int4(0, 0, 0, 0);
    for (; i < n4; i += stride) a[i] = z;
}

__global__ void build_wcat_kernel(const float* __restrict__ w1l,
                                  const float* __restrict__ w1r,
                                  const float* __restrict__ w2l,
                                  const float* __restrict__ w2r,
                                  float* __restrict__ wcat,
                                  float* __restrict__ wcat2) {
    int i = blockIdx.x * blockDim.x + threadIdx.x;
    if (i < F * 256) {
        int k = i >> 8, c = i & 255;
        wcat[i] = (c < 128) ? w1l[k * 128 + c] : w1r[k * 128 + (c - 128)];
    } else if (i < F * 256 + F * 80) {
        int j = i - F * 256;
        int k = j / 80, c = j % 80;
        wcat2[j] = (c < NCLS) ? w2l[k * NCLS + c] : w2r[k * NCLS + (c - NCLS)];
    }
}

__global__ void hist_kernel(const void* __restrict__ ei,
                            int* __restrict__ src32, int* __restrict__ dst32,
                            int* __restrict__ cnt, int E) {
    const int mode32 = g_mode32;
    int stride = gridDim.x * blockDim.x;
    for (int e = blockIdx.x * blockDim.x + threadIdx.x; e < E; e += stride) {
        int s, d;
        if (mode32) {
            const int* p = (const int*)ei;
            s = p[e]; d = p[E + e];
        } else {
            const long long* p = (const long long*)ei;
            s = (int)p[e]; d = (int)p[E + e];
        }
        src32[e] = s;
        dst32[e] = d;
        atomicAdd(&cnt[d], 1);
    }
}

__global__ void scan1_kernel(const int* __restrict__ cnt,
                             int* __restrict__ incl, int* __restrict__ bsum) {
    __shared__ int sm[SCB];
    int t = threadIdx.x;
    int i = blockIdx.x * SCB + t;
    int v = (i < NN) ? cnt[i] : 0;
    sm[t] = v;
    __syncthreads();
    for (int off = 1; off < SCB; off <<= 1) {
        int x = (t >= off) ? sm[t - off] : 0;
        __syncthreads();
        sm[t] += x;
        __syncthreads();
    }
    if (i < NN) incl[i] = sm[t];
    if (t == SCB - 1) bsum[blockIdx.x] = sm[t];
}

__global__ void scan2_kernel(const int* __restrict__ bsum, int* __restrict__ bexc) {
    __shared__ int sm[128];
    int t = threadIdx.x;
    int v = (t < NSB) ? bsum[t] : 0;
    sm[t] = v;
    __syncthreads();
    for (int off = 1; off < 128; off <<= 1) {
        int x = (t >= off) ? sm[t - off] : 0;
        __syncthreads();
        sm[t] += x;
        __syncthreads();
    }
    if (t < NSB) bexc[t] = sm[t] - v;
}

__global__ void scan3_kernel(const int* __restrict__ incl,
                             const int* __restrict__ cnt,
                             const int* __restrict__ bexc,
                             int* __restrict__ offs) {
    int i = blockIdx.x * blockDim.x + threadIdx.x;
    if (i < NN) offs[i] = incl[i] - cnt[i] + bexc[i >> 9];
}

__global__ void fill_kernel(const int* __restrict__ src32,
                            const int* __restrict__ dst32,
                            int* __restrict__ offs, int* __restrict__ csr, int E) {
    int stride = gridDim.x * blockDim.x;
    for (int e = blockIdx.x * blockDim.x + threadIdx.x; e < E; e += stride) {
        int d = dst32[e];
        int slot = atomicAdd(&offs[d], 1);
        csr[slot] = src32[e];
    }
}

// ---------------------------------------------------------------------------
// 3xTF32 tensor-core GEMM: C[N x ...] = A[N x 128] @ B, fp32-accurate.
//   a = hi(a) + lo(a); acc += hi_a*hi_b + hi_a*lo_b + lo_a*hi_b  (lo*lo ~2^-24)
// BM=128, BN per blockIdx.y, K staged in two 64-wide smem halves.
// 8 warps as 4(m) x 2(n); warp tile 32 x BN/2; mma.m16n8k8.
__device__ __forceinline__ void f2tf32x(float a, uint32_t& hi, uint32_t& lo) {
    asm("cvt.rna.tf32.f32 %0, %1;" : "=r"(hi) : "f"(a));
    float r = a - __uint_as_float(hi);
    asm("cvt.rna.tf32.f32 %0, %1;" : "=r"(lo) : "f"(r));
}

#define MMA_TF32(c, a, b0, b1)                                              \
    asm volatile(                                                           \
        "mma.sync.aligned.m16n8k8.row.col.f32.tf32.tf32.f32 "               \
        "{%0,%1,%2,%3},{%4,%5,%6,%7},{%8,%9},{%0,%1,%2,%3};"                \
        : "+f"((c)[0]), "+f"((c)[1]), "+f"((c)[2]), "+f"((c)[3])            \
        : "r"((a)[0]), "r"((a)[1]), "r"((a)[2]), "r"((a)[3]),               \
          "r"(b0), "r"(b1))

template <int BN, int SWB, int SWC>
__global__ __launch_bounds__(256, 2)
void gemm_tc_kernel(const float* __restrict__ A,
                    const float* __restrict__ B,
                    float* __restrict__ C,
                    int Nrows) {
    constexpr int NWT = BN / 16;       // n-tiles (of 8) per warp
    constexpr int KP = 68;             // padded k-stride (68%32=4 -> conflict-free frags)
    extern __shared__ float sm[];
    float* As = sm;                    // [128][KP]  (m-major)
    float* Bs = sm + 128 * KP;         // [BN][KP]   (n-major, i.e. B transposed)

    int tid = threadIdx.x;
    int lane = tid & 31;
    int warp = tid >> 5;
    int g = lane >> 2, tig = lane & 3;
    int warpRow = warp & 3, warpCol = warp >> 2;
    int brow = blockIdx.x * 128;
    int colbase = blockIdx.y * 128;

    float acc[2][NWT][4];
#pragma unroll
    for (int mt = 0; mt < 2; mt++)
#pragma unroll
        for (int nt = 0; nt < NWT; nt++)
#pragma unroll
            for (int j = 0; j < 4; j++) acc[mt][nt][j] = 0.0f;

#pragma unroll
    for (int kh = 0; kh < 2; kh++) {
        int kc = kh * 64;
        if (kh) __syncthreads();       // protect smem reuse
        // --- load A half-tile (128 x 64): 8 float4 per thread
#pragma unroll
        for (int p = 0; p < 8; p++) {
            int idx = tid + p * 256;           // 0..2047
            int m = idx >> 4;
            int kq = (idx & 15) << 2;
            float4 v = make_float4(0.f, 0.f, 0.f, 0.f);
            if (brow + m < Nrows)
                v = *(const float4*)(A + (size_t)(brow + m) * F + kc + kq);
            *(float4*)(As + m * KP + kq) = v;
        }
        // --- load B half-tile (64 x BN) transposed into Bs[n][k]
        constexpr int BF4 = 64 * BN / 4 / 256;
#pragma unroll
        for (int p = 0; p < BF4; p++) {
            int idx = tid + p * 256;
            int kk = idx / (BN / 4);
            int n4 = (idx % (BN / 4)) * 4;
            float4 v = *(const float4*)(B + (size_t)(kc + kk) * SWB + colbase + n4);
            Bs[(n4 + 0) * KP + kk] = v.x;
            Bs[(n4 + 1) * KP + kk] = v.y;
            Bs[(n4 + 2) * KP + kk] = v.z;
            Bs[(n4 + 3) * KP + kk] = v.w;
        }
        __syncthreads();

#pragma unroll
        for (int k8 = 0; k8 < 8; k8++) {
            int kb = k8 * 8;
            uint32_t ah[2][4], al[2][4];
#pragma unroll
            for (int mt = 0; mt < 2; mt++) {
                const float* ap = As + (warpRow * 32 + mt * 16 + g) * KP + kb;
                f2tf32x(ap[tig],            ah[mt][0], al[mt][0]);
                f2tf32x(ap[8 * KP + tig],   ah[mt][1], al[mt][1]);
                f2tf32x(ap[tig + 4],        ah[mt][2], al[mt][2]);
                f2tf32x(ap[8 * KP + tig+4], ah[mt][3], al[mt][3]);
            }
#pragma unroll
            for (int nt = 0; nt < NWT; nt++) {
                const float* bp = Bs + (warpCol * (BN / 2) + nt * 8 + g) * KP + kb;
                uint32_t bh0, bl0, bh1, bl1;
                f2tf32x(bp[tig],     bh0, bl0);
                f2tf32x(bp[tig + 4], bh1, bl1);
#pragma unroll
                for (int mt = 0; mt < 2; mt++) {
                    MMA_TF32(acc[mt][nt], ah[mt], bh0, bh1);
                    MMA_TF32(acc[mt][nt], ah[mt], bl0, bl1);
                    MMA_TF32(acc[mt][nt], al[mt], bh0, bh1);
                }
            }
        }
    }

    // epilogue: c0,c1 = (row, 2tig..2tig+1), c2,c3 = (row+8, ...)
#pragma unroll
    for (int mt = 0; mt < 2; mt++) {
#pragma unroll
        for (int nt = 0; nt < NWT; nt++) {
            int row0 = brow + warpRow * 32 + mt * 16 + g;
            int col = colbase + warpCol * (BN / 2) + nt * 8 + 2 * tig;
            if (row0 < Nrows) {
                float2 v = make_float2(acc[mt][nt][0], acc[mt][nt][1]);
                *(float2*)(C + (size_t)row0 * SWC + col) = v;
            }
            if (row0 + 8 < Nrows) {
                float2 v = make_float2(acc[mt][nt][2], acc[mt][nt][3]);
                *(float2*)(C + (size_t)(row0 + 8) * SWC + col) = v;
            }
        }
    }
}

// ---------------------------------------------------------------------------
// Layer-1 aggregation + epilogue: h[n] = relu(mean_{s in N(n)} p[s] + t[n] + b1)
__global__ void agg1_kernel(const int* __restrict__ csr,
                            const int* __restrict__ offs,
                            const int* __restrict__ cnt,
                            const float* __restrict__ pt,
                            const float* __restrict__ b1,
                            float* __restrict__ h) {
    int gw = (blockIdx.x * blockDim.x + threadIdx.x) >> 5;
    int lane = threadIdx.x & 31;
    if (gw >= NN) return;
    int dg = cnt[gw];
    int beg = offs[gw] - dg;
    float4 acc0 = make_float4(0.f, 0.f, 0.f, 0.f);
    float4 acc1 = make_float4(0.f, 0.f, 0.f, 0.f);
    int i = 0;
    for (; i + 4 <= dg; i += 4) {
        int s0 = __ldg(&csr[beg + i]);
        int s1 = __ldg(&csr[beg + i + 1]);
        int s2 = __ldg(&csr[beg + i + 2]);
        int s3 = __ldg(&csr[beg + i + 3]);
        float4 v0 = *(const float4*)(pt + (long long)s0 * 256 + lane * 4);
        float4 v1 = *(const float4*)(pt + (long long)s1 * 256 + lane * 4);
        float4 v2 = *(const float4*)(pt + (long long)s2 * 256 + lane * 4);
        float4 v3 = *(const float4*)(pt + (long long)s3 * 256 + lane * 4);
        acc0.x += v0.x + v1.x; acc0.y += v0.y + v1.y;
        acc0.z += v0.z + v1.z; acc0.w += v0.w + v1.w;
        acc1.x += v2.x + v3.x; acc1.y += v2.y + v3.y;
        acc1.z += v2.z + v3.z; acc1.w += v2.w + v3.w;
    }
    for (; i < dg; i++) {
        int s = __ldg(&csr[beg + i]);
        float4 v = *(const float4*)(pt + (long long)s * 256 + lane * 4);
        acc0.x += v.x; acc0.y += v.y; acc0.z += v.z; acc0.w += v.w;
    }
    float inv = 1.0f / fmaxf((float)dg, 1.0f);
    float4 t = *(const float4*)(pt + (long long)gw * 256 + 128 + lane * 4);
    float4 bb = *(const float4*)(b1 + lane * 4);
    float4 r;
    r.x = fmaxf((acc0.x + acc1.x) * inv + t.x + bb.x, 0.f);
    r.y = fmaxf((acc0.y + acc1.y) * inv + t.y + bb.y, 0.f);
    r.z = fmaxf((acc0.z + acc1.z) * inv + t.z + bb.z, 0.f);
    r.w = fmaxf((acc0.w + acc1.w) * inv + t.w + bb.w, 0.f);
    *(float4*)(h + (long long)gw * F + lane * 4) = r;
}

// Layer-2: out[n] = mean q[s] + u[n] + b2. qu stride 80: q=0:40, u=40:80.
__global__ void agg2_kernel(const int* __restrict__ csr,
                            const int* __restrict__ offs,
                            const int* __restrict__ cnt,
                            const float* __restrict__ qu,
                            const float* __restrict__ b2,
                            float* __restrict__ out) {
    int gw = (blockIdx.x * blockDim.x + threadIdx.x) >> 5;
    int lane = threadIdx.x & 31;
    if (gw >= NN) return;
    int dg = cnt[gw];
    int beg = offs[gw] - dg;
    if (lane < 10) {
        float4 acc0 = make_float4(0.f, 0.f, 0.f, 0.f);
        float4 acc1 = make_float4(0.f, 0.f, 0.f, 0.f);
        int i = 0;
        for (; i + 4 <= dg; i += 4) {
            int s0 = __ldg(&csr[beg + i]);
            int s1 = __ldg(&csr[beg + i + 1]);
            int s2 = __ldg(&csr[beg + i + 2]);
            int s3 = __ldg(&csr[beg + i + 3]);
            float4 v0 = *(const float4*)(qu + (long long)s0 * 80 + lane * 4);
            float4 v1 = *(const float4*)(qu + (long long)s1 * 80 + lane * 4);
            float4 v2 = *(const float4*)(qu + (long long)s2 * 80 + lane * 4);
            float4 v3 = *(const float4*)(qu + (long long)s3 * 80 + lane * 4);
            acc0.x += v0.x + v1.x; acc0.y += v0.y + v1.y;
            acc0.z += v0.z + v1.z; acc0.w += v0.w + v1.w;
            acc1.x += v2.x + v3.x; acc1.y += v2.y + v3.y;
            acc1.z += v2.z + v3.z; acc1.w += v2.w + v3.w;
        }
        for (; i < dg; i++) {
            int s = __ldg(&csr[beg + i]);
            float4 v = *(const float4*)(qu + (long long)s * 80 + lane * 4);
            acc0.x += v.x; acc0.y += v.y; acc0.z += v.z; acc0.w += v.w;
        }
        float inv = 1.0f / fmaxf((float)dg, 1.0f);
        float4 uv = *(const float4*)(qu + (long long)gw * 80 + NCLS + lane * 4);
        float4 bb = *(const float4*)(b2 + lane * 4);
        float4 r;
        r.x = (acc0.x + acc1.x) * inv + uv.x + bb.x;
        r.y = (acc0.y + acc1.y) * inv + uv.y + bb.y;
        r.z = (acc0.z + acc1.z) * inv + uv.z + bb.z;
        r.w = (acc0.w + acc1.w) * inv + uv.w + bb.w;
        *(float4*)(out + (long long)gw * NCLS + lane * 4) = r;
    }
}

// ---------------------------------------------------------------------------
extern "C" void kernel_launch(void* const* d_in, const int* in_sizes, int n_in,
                              void* d_out, int out_size) {
    const float* x   = (const float*)d_in[0];
    const void*  ei  = d_in[1];
    const float* w1l = (const float*)d_in[2];
    const float* w1r = (const float*)d_in[3];
    const float* b1  = (const float*)d_in[4];
    const float* w2l = (const float*)d_in[5];
    const float* w2r = (const float*)d_in[6];
    const float* b2  = (const float*)d_in[7];
    float* out = (float*)d_out;

    int E = in_sizes[1] / 2;
    int N = in_sizes[0] / F;   // 50000

    float *pPT, *pH, *pWcat, *pWcat2;
    int *pSrc, *pDst, *pCsr, *pCnt, *pOffs, *pIncl, *pBsum, *pBexc;
    cudaGetSymbolAddress((void**)&pPT,    g_pt);
    cudaGetSymbolAddress((void**)&pH,     g_h);
    cudaGetSymbolAddress((void**)&pWcat,  g_wcat);
    cudaGetSymbolAddress((void**)&pWcat2, g_wcat2);
    cudaGetSymbolAddress((void**)&pSrc,   g_src);
    cudaGetSymbolAddress((void**)&pDst,   g_dst);
    cudaGetSymbolAddress((void**)&pCsr,   g_csr);
    cudaGetSymbolAddress((void**)&pCnt,   g_cnt);
    cudaGetSymbolAddress((void**)&pOffs,  g_offs);
    cudaGetSymbolAddress((void**)&pIncl,  g_incl);
    cudaGetSymbolAddress((void**)&pBsum,  g_bsum);
    cudaGetSymbolAddress((void**)&pBexc,  g_bexc);

    const int T = 256;
    int gemm_rows = (N + 127) / 128;          // 391
    int edge_blocks = (E + T - 1) / T;        // 2344
    int warp_blocks = (N * 32 + T - 1) / T;   // 6250

    // dynamic smem opt-in for the tensor-core GEMMs (idempotent host calls)
    const int SMEM1 = (128 + 128) * 68 * 4;   // 69632
    const int SMEM2 = (128 + 80) * 68 * 4;    // 56576
    cudaFuncSetAttribute(gemm_tc_kernel<128, 256, 256>,
                         cudaFuncAttributeMaxDynamicSharedMemorySize, SMEM1);
    cudaFuncSetAttribute(gemm_tc_kernel<80, 80, 80>,
                         cudaFuncAttributeMaxDynamicSharedMemorySize, SMEM2);

    // Fork-join resources (host-side only; created per call, not destroyed).
    cudaStream_t s2 = 0;
    cudaEvent_t eA = 0, eB = 0;
    bool forked = (cudaStreamCreateWithFlags(&s2, cudaStreamNonBlocking) == cudaSuccess);
    if (forked) forked = (cudaEventCreateWithFlags(&eA, cudaEventDisableTiming) == cudaSuccess);
    if (forked) forked = (cudaEventCreateWithFlags(&eB, cudaEventDisableTiming) == cudaSuccess);
    cudaStream_t sb = forked ? s2 : (cudaStream_t)0;

    // --- main stream: 1 detect, 2 zero, 3 wcat ---
    detect_kernel<<<1, 32>>>(ei);
    zero_int_kernel<<<64, T>>>((int4*)pCnt, NN / 4 + 1);
    build_wcat_kernel<<<(F * 256 + F * 80 + T - 1) / T, T>>>(
        w1l, w1r, w2l, w2r, pWcat, pWcat2);

    // fork
    if (forked) {
        cudaEventRecord(eA, 0);
        cudaStreamWaitEvent(s2, eA, 0);
    }

    // 4: layer-1 tensor-core GEMM (profiled launch)
    gemm_tc_kernel<128, 256, 256><<<dim3(gemm_rows, 2), T, SMEM1>>>(
        x, pWcat, pPT, N);

    // CSR chain on branch stream (overlaps gemm1)
    hist_kernel<<<edge_blocks, T, 0, sb>>>(ei, pSrc, pDst, pCnt, E);
    scan1_kernel<<<NSB, SCB, 0, sb>>>(pCnt, pIncl, pBsum);
    scan2_kernel<<<1, 128, 0, sb>>>(pBsum, pBexc);
    scan3_kernel<<<(NN + T - 1) / T, T, 0, sb>>>(pIncl, pCnt, pBexc, pOffs);
    fill_kernel<<<edge_blocks, T, 0, sb>>>(pSrc, pDst, pOffs, pCsr, E);

    // join
    if (forked) {
        cudaEventRecord(eB, s2);
        cudaStreamWaitEvent((cudaStream_t)0, eB, 0);
    }

    // layer-1 aggregation + epilogue -> h
    agg1_kernel<<<warp_blocks, T>>>(pCsr, pOffs, pCnt, pPT, b1, pH);
    // layer-2 tensor-core GEMM  qu = h @ [w2l|w2r]
    gemm_tc_kernel<80, 80, 80><<<dim3(gemm_rows, 1), T, SMEM2>>>(
        pH, pWcat2, pPT, N);
    // layer-2 aggregation + epilogue -> out
    agg2_kernel<<<warp_blocks, T>>>(pCsr, pOffs, pCnt, pPT, b2, out);
}